// round 13
// baseline (speedup 1.0000x reference)
#include <cuda_runtime.h>
#include <cstdint>

#define NS 2
#define NB 8
#define NC 32
#define NH 128
#define NW 128
#define NM 32
#define RH 64
#define RW 64

// One block = one (n, bm, c) output tile of 64x64 floats (16 KB).
// 256 threads; each thread writes 4 float4s at rows r0, r0+16, r0+32, r0+48.
// Loads fetch EXACTLY the needed window [x1+c0, x1+c0+4) with alignment-legal
// pieces (x1 parity block-uniform). Stores: DEFAULT policy (evict-normal) —
// single-variable experiment vs the __stcs variants (all ~48-50us): lets L2
// accumulate dirty lines and batch DRAM writebacks instead of eager eviction.

__global__ __launch_bounds__(256) void roi_patch_kernel(
    const float* __restrict__ fm,
    const int*   __restrict__ boxes,
    float*       __restrict__ out)
{
    const int blk = blockIdx.x;
    const int c   = blk & 31;
    const int bm  = (blk >> 5) & 255;
    const int n   = blk >> 13;
    const int b   = bm >> 5;
    const int m   = bm & 31;

    const int4 box = __ldg(reinterpret_cast<const int4*>(boxes)
                           + (n * NB + b) * NM + m);
    const int x1   = box.x;
    const int y1   = box.y;
    const int wbox = box.z - x1;   // valid cols: cc < wbox  (8..64)
    const int hbox = box.w - y1;   // valid rows: r  < hbox  (8..64)

    const int lane16 = threadIdx.x & 15;
    const int r0     = threadIdx.x >> 4;     // 0..15
    const int c0     = lane16 << 2;

    const bool p0 = (c0 + 0) < wbox;
    const bool p1 = (c0 + 1) < wbox;
    const bool p2 = (c0 + 2) < wbox;
    const bool p3 = (c0 + 3) < wbox;

    const float* s0 = fm
        + (((size_t)(n * NB + b) * NC + c) * NH + (y1 + r0)) * NW
        + x1 + c0;
    float* dst = out + ((size_t)blk << 12) + (r0 << 6) + c0;

    if ((x1 & 1) == 0) {
        // 8B-aligned window: two LDG.64 pieces.
        #pragma unroll
        for (int i = 0; i < 4; ++i) {
            const int r = r0 + (i << 4);
            float4 v = make_float4(0.f, 0.f, 0.f, 0.f);
            if (r < hbox) {
                const float* s = s0 + (i << 4) * NW;
                if (p0) {
                    const float2 lo = __ldg(reinterpret_cast<const float2*>(s));
                    v.x = lo.x; v.y = lo.y;
                }
                if (p2) {
                    const float2 hi = __ldg(reinterpret_cast<const float2*>(s + 2));
                    v.z = hi.x; v.w = hi.y;
                }
                if (!p1) v.y = 0.f;
                if (!p3) v.w = 0.f;
            }
            *reinterpret_cast<float4*>(dst + ((i << 4) << 6)) = v;
        }
    } else {
        // 4B-aligned window: LDG.32 + LDG.64 (s+1 is 8B-aligned) + LDG.32.
        #pragma unroll
        for (int i = 0; i < 4; ++i) {
            const int r = r0 + (i << 4);
            float4 v = make_float4(0.f, 0.f, 0.f, 0.f);
            if (r < hbox) {
                const float* s = s0 + (i << 4) * NW;
                if (p0) v.x = __ldg(s);
                if (p1) {
                    const float2 mid = __ldg(reinterpret_cast<const float2*>(s + 1));
                    v.y = mid.x; v.z = mid.y;
                }
                if (p3) v.w = __ldg(s + 3);
                if (!p2) v.z = 0.f;
            }
            *reinterpret_cast<float4*>(dst + ((i << 4) << 6)) = v;
        }
    }
}

extern "C" void kernel_launch(void* const* d_in, const int* in_sizes, int n_in,
                              void* d_out, int out_size)
{
    const float* fm    = (const float*)d_in[0];
    const int*   boxes = (const int*)d_in[1];
    float*       out   = (float*)d_out;

    const int blocks = NS * NB * NM * NC;   // 16384 tiles
    roi_patch_kernel<<<blocks, 256>>>(fm, boxes, out);
}

// round 15
// speedup vs baseline: 1.1167x; 1.1167x over previous
#include <cuda_runtime.h>
#include <cstdint>

#define NS 2
#define NB 8
#define NC 32
#define NH 128
#define NW 128
#define NM 32
#define RH 64
#define RW 64

// FINAL: best-measured configuration (48.06us wall, rel_err 0).
//
// One block = one (n, bm, c) output tile of 64x64 floats (16 KB).
// 256 threads; each thread writes 4 float4s at rows r0, r0+16, r0+32, r0+48.
// x1 alignment (off = x1 & 3) is block-uniform -> compile-time-shift bodies.
// Aligned A/B float4 loads + register compose; STG.128.CS streaming stores.
//
// Experiment ledger (10+ rounds): load-mix variants, MLP batching, 2x
// per-thread work, bulk-async (TMA) stores (single + double-buffered), SMEM
// plane residency, and L2 store-policy were all neutral or regressions. HBM
// traffic equals the mandatory 256 MB output write stream (reads are
// L2-resident); the kernel sits at the DRAM write-bandwidth wall
// (~4.8-5 TB/s effective). R14 was an infra failure; resubmitting unchanged.

template <int OFF>
__device__ __forceinline__ void tile_body(
    const float* __restrict__ srcA,   // aligned: plane + (y1+r0)*NW + (x1-OFF) + c0
    float* __restrict__ dst,          // out tile + r0*64 + c0
    int r0, int c0, int hbox, int wbox)
{
    const bool cv  = c0 < wbox;        // any column of this float4 valid
    const bool m1  = (c0 + 1) < wbox;
    const bool m2  = (c0 + 2) < wbox;
    const bool m3  = (c0 + 3) < wbox;

    #pragma unroll
    for (int i = 0; i < 4; ++i) {
        const int r = r0 + (i << 4);
        float4 val = make_float4(0.f, 0.f, 0.f, 0.f);
        if (r < hbox && cv) {
            const float4* p = reinterpret_cast<const float4*>(srcA + (i << 4) * NW);
            const float4 A = __ldg(p);
            if (OFF == 0) {
                val = A;
            } else {
                const float4 B = __ldg(p + 1);
                if (OFF == 1) val = make_float4(A.y, A.z, A.w, B.x);
                if (OFF == 2) val = make_float4(A.z, A.w, B.x, B.y);
                if (OFF == 3) val = make_float4(A.w, B.x, B.y, B.z);
            }
            if (!m1) val.y = 0.f;
            if (!m2) val.z = 0.f;
            if (!m3) val.w = 0.f;
        }
        __stcs(reinterpret_cast<float4*>(dst + ((i << 4) << 6)), val);
    }
}

__global__ __launch_bounds__(256) void roi_patch_kernel(
    const float* __restrict__ fm,
    const int*   __restrict__ boxes,
    float*       __restrict__ out)
{
    const int blk = blockIdx.x;
    const int c   = blk & 31;
    const int bm  = (blk >> 5) & 255;
    const int n   = blk >> 13;
    const int b   = bm >> 5;
    const int m   = bm & 31;

    __shared__ int4 sbox;
    if (threadIdx.x == 0) {
        sbox = reinterpret_cast<const int4*>(boxes)[(n * NB + b) * NM + m];
    }
    __syncthreads();

    const int x1   = sbox.x;
    const int y1   = sbox.y;
    const int wbox = sbox.z - x1;   // valid cols: cc < wbox  (8..64)
    const int hbox = sbox.w - y1;   // valid rows: r  < hbox  (8..64)
    const int off  = x1 & 3;        // block-uniform

    const int lane16 = threadIdx.x & 15;
    const int r0     = threadIdx.x >> 4;     // 0..15
    const int c0     = lane16 << 2;

    const float* srcA = fm
        + (((size_t)(n * NB + b) * NC + c) * NH + (y1 + r0)) * NW
        + (x1 - off) + c0;                   // 16B-aligned
    float* dst = out + ((size_t)blk << 12) + (r0 << 6) + c0;

    switch (off) {
        case 0: tile_body<0>(srcA, dst, r0, c0, hbox, wbox); break;
        case 1: tile_body<1>(srcA, dst, r0, c0, hbox, wbox); break;
        case 2: tile_body<2>(srcA, dst, r0, c0, hbox, wbox); break;
        default: tile_body<3>(srcA, dst, r0, c0, hbox, wbox); break;
    }
}

extern "C" void kernel_launch(void* const* d_in, const int* in_sizes, int n_in,
                              void* d_out, int out_size)
{
    const float* fm    = (const float*)d_in[0];
    const int*   boxes = (const int*)d_in[1];
    float*       out   = (float*)d_out;

    const int blocks = NS * NB * NM * NC;   // 16384 tiles
    roi_patch_kernel<<<blocks, 256>>>(fm, boxes, out);
}